// round 6
// baseline (speedup 1.0000x reference)
#include <cuda_runtime.h>
#include <cuda_bf16.h>
#include <cstdint>
#include <math.h>

#define NN 200000
#define NE 600000
#define NG 8192
#define DIN 64
#define HD 128
#define NL 4
#define LNEPS 1e-5f

// ---------------- scratch (device globals, no allocations) ----------------
__device__ float g_h   [(size_t)NN * HD];
__device__ float g_hw  [(size_t)NN * HD];
__device__ float g_agg [(size_t)NN * HD];   // also reused as phys tmp
__device__ float g_gw  [(size_t)NG * HD];
__device__ float g_gemb[(size_t)NG * HD];
__device__ float g_dis [NN];
__device__ int   g_cnt [NN];
__device__ int   g_cur [NN];
__device__ int   g_off [NN + 1];
__device__ int   g_srcs[NE];

// weights split to bf16 hi/lo
__device__ __nv_bfloat16 w_in_hi[128 * DIN],     w_in_lo[128 * DIN];
__device__ __nv_bfloat16 w_cv_hi[NL * 128 * HD], w_cv_lo[NL * 128 * HD];
__device__ __nv_bfloat16 w_p1_hi[128 * HD],      w_p1_lo[128 * HD];
__device__ __nv_bfloat16 w_p2_hi[128 * HD],      w_p2_lo[128 * HD];
__device__ __nv_bfloat16 w_ha_hi[128 * HD],      w_ha_lo[128 * HD];
__device__ __nv_bfloat16 w_hb_hi[128 * HD],      w_hb_lo[128 * HD];

// ---------------- CSR build ----------------
__global__ void zero_cnt_kernel() {
    int i = blockIdx.x * blockDim.x + threadIdx.x;
    if (i < NN) { g_cnt[i] = 0; g_cur[i] = 0; }
}
__global__ void hist_kernel(const int* __restrict__ ei) {
    int e = blockIdx.x * blockDim.x + threadIdx.x;
    if (e < NE) atomicAdd(&g_cnt[ei[NE + e]], 1);
}
__global__ void scan_kernel() {   // single block, 1024 threads
    const int t = threadIdx.x;
    const int lane = t & 31, wid = t >> 5;
    __shared__ int wsum[32];
    __shared__ int runS;
    if (t == 0) runS = 0;
    __syncthreads();
    for (int base = 0; base < NN; base += 1024) {
        int idx = base + t;
        int v = (idx < NN) ? g_cnt[idx] : 0;
        int x = v;
#pragma unroll
        for (int o = 1; o < 32; o <<= 1) {
            int y = __shfl_up_sync(0xffffffffu, x, o);
            if (lane >= o) x += y;
        }
        if (lane == 31) wsum[wid] = x;
        __syncthreads();
        if (wid == 0) {
            int w = wsum[lane];
#pragma unroll
            for (int o = 1; o < 32; o <<= 1) {
                int y = __shfl_up_sync(0xffffffffu, w, o);
                if (lane >= o) w += y;
            }
            wsum[lane] = w;
        }
        __syncthreads();
        int excl = x - v + (wid ? wsum[wid - 1] : 0) + runS;
        if (idx < NN) g_off[idx] = excl;
        int tot = wsum[31];
        __syncthreads();
        if (t == 0) runS += tot;
        __syncthreads();
    }
    if (t == 0) g_off[NN] = runS;
}
__global__ void dis_kernel() {
    int i = blockIdx.x * blockDim.x + threadIdx.x;
    if (i < NN) g_dis[i] = rsqrtf((float)g_cnt[i] + 1.f);
}
__global__ void fill_kernel(const int* __restrict__ ei) {
    int e = blockIdx.x * blockDim.x + threadIdx.x;
    if (e >= NE) return;
    int s = ei[e], d = ei[NE + e];
    int pos = g_off[d] + atomicAdd(&g_cur[d], 1);
    g_srcs[pos] = s;
}

// ---------------- weight conversion ----------------
__global__ void convert_w2_kernel(const float* __restrict__ src, int lds, int K,
                                  __nv_bfloat16* __restrict__ whi,
                                  __nv_bfloat16* __restrict__ wlo) {
    int i = blockIdx.x * blockDim.x + threadIdx.x;
    if (i >= 128 * K) return;
    int j = i / K, k = i - j * K;
    float v = src[(size_t)j * lds + k];
    __nv_bfloat16 hi = __float2bfloat16(v);
    whi[i] = hi;
    wlo[i] = __float2bfloat16(v - __bfloat162float(hi));
}

// ---------------- aggregation: agg[d] = h[d]*dis[d]^2 + sum_src h[s]*dis[s]*dis[d] --
__global__ void aggregate_kernel() {
    int d = (blockIdx.x * blockDim.x + threadIdx.x) >> 5;
    int lane = threadIdx.x & 31;
    if (d >= NN) return;
    int beg = g_off[d], end = g_off[d + 1];
    float dd = g_dis[d];
    float sn = dd * dd;
    float4 acc = *reinterpret_cast<const float4*>(&g_h[(size_t)d * HD + lane * 4]);
    acc.x *= sn; acc.y *= sn; acc.z *= sn; acc.w *= sn;
    for (int e = beg; e < end; e++) {
        int s = g_srcs[e];
        float ne = g_dis[s] * dd;
        float4 v = *reinterpret_cast<const float4*>(&g_h[(size_t)s * HD + lane * 4]);
        acc.x += v.x * ne; acc.y += v.y * ne; acc.z += v.z * ne; acc.w += v.w * ne;
    }
    *reinterpret_cast<float4*>(&g_agg[(size_t)d * HD + lane * 4]) = acc;
}

// ---------------- tensor-core GEMM with in-kernel hi/lo split -----------------
// C[n][j] = epilogue( sum_k A[n][k]*W[j][k] ), A f32 [nrows][K], W bf16 hi/lo [128][K].
__device__ __forceinline__ void mma_bf16(float4& c, unsigned a0, unsigned a1, unsigned a2,
                                         unsigned a3, unsigned b0, unsigned b1) {
    asm volatile(
        "mma.sync.aligned.m16n8k16.row.col.f32.bf16.bf16.f32 "
        "{%0,%1,%2,%3}, {%4,%5,%6,%7}, {%8,%9}, {%0,%1,%2,%3};"
        : "+f"(c.x), "+f"(c.y), "+f"(c.z), "+f"(c.w)
        : "r"(a0), "r"(a1), "r"(a2), "r"(a3), "r"(b0), "r"(b1));
}

template<int K, bool SILU_, bool BIAS, bool GATHER, bool RES, bool LN, bool DOT>
__launch_bounds__(256)
__global__ void gemm_tc(const float* __restrict__ A,
                        const __nv_bfloat16* __restrict__ Whi,
                        const __nv_bfloat16* __restrict__ Wlo,
                        const float* __restrict__ bias,
                        const float* __restrict__ gtab, const int* __restrict__ gidx,
                        const float* __restrict__ Rsrc,
                        const float* __restrict__ lng, const float* __restrict__ lnb,
                        const float* __restrict__ w2, const float* __restrict__ w2b,
                        float* __restrict__ C, int nrows)
{
    __shared__ __nv_bfloat16 As[128][72];
    __shared__ __nv_bfloat16 Bs[128][72];
    __shared__ float redS[128];
    __shared__ float redQ[128];

    const int t    = threadIdx.x;
    const int lane = t & 31;
    const int wid  = t >> 5;
    const int wm   = wid >> 2;    // 0..1
    const int wn   = wid & 3;     // 0..3
    const int g    = lane >> 2;   // 0..7
    const int tg   = lane & 3;    // 0..3
    const int rowBase = blockIdx.x * 128;

    float4 acc[4][4];
#pragma unroll
    for (int i = 0; i < 4; i++)
#pragma unroll
        for (int j = 0; j < 4; j++) acc[i][j] = make_float4(0.f, 0.f, 0.f, 0.f);

    auto loadA = [&](int k0, bool want_lo) {
#pragma unroll
        for (int q = 0; q < 8; q++) {
            int f = t + 256 * q;
            int r = f >> 4;
            int c = (f & 15) * 4;
            float4 v = make_float4(0.f, 0.f, 0.f, 0.f);
            int grow = rowBase + r;
            if (grow < nrows)
                v = *reinterpret_cast<const float4*>(&A[(size_t)grow * K + k0 + c]);
            __nv_bfloat16 b0, b1, b2, b3;
            if (!want_lo) {
                b0 = __float2bfloat16(v.x); b1 = __float2bfloat16(v.y);
                b2 = __float2bfloat16(v.z); b3 = __float2bfloat16(v.w);
            } else {
                __nv_bfloat16 h0 = __float2bfloat16(v.x), h1 = __float2bfloat16(v.y);
                __nv_bfloat16 h2 = __float2bfloat16(v.z), h3 = __float2bfloat16(v.w);
                b0 = __float2bfloat16(v.x - __bfloat162float(h0));
                b1 = __float2bfloat16(v.y - __bfloat162float(h1));
                b2 = __float2bfloat16(v.z - __bfloat162float(h2));
                b3 = __float2bfloat16(v.w - __bfloat162float(h3));
            }
            *reinterpret_cast<__nv_bfloat162*>(&As[r][c])     = __halves2bfloat162(b0, b1);
            *reinterpret_cast<__nv_bfloat162*>(&As[r][c + 2]) = __halves2bfloat162(b2, b3);
        }
    };
    auto loadB = [&](const __nv_bfloat16* __restrict__ W, int k0) {
#pragma unroll
        for (int q = 0; q < 4; q++) {
            int f = t + 256 * q;
            int r = f >> 3, sub = f & 7;
            *reinterpret_cast<uint4*>(&Bs[r][sub * 8]) =
                *reinterpret_cast<const uint4*>(&W[(size_t)r * K + k0 + sub * 8]);
        }
    };
    auto mmas = [&]() {
#pragma unroll
        for (int ks = 0; ks < 4; ks++) {
            unsigned a[4][4], b[4][2];
#pragma unroll
            for (int mt = 0; mt < 4; mt++) {
                int rm = wm * 64 + mt * 16;
                a[mt][0] = *reinterpret_cast<const unsigned*>(&As[rm + g    ][ks * 16 + tg * 2]);
                a[mt][1] = *reinterpret_cast<const unsigned*>(&As[rm + g + 8][ks * 16 + tg * 2]);
                a[mt][2] = *reinterpret_cast<const unsigned*>(&As[rm + g    ][ks * 16 + tg * 2 + 8]);
                a[mt][3] = *reinterpret_cast<const unsigned*>(&As[rm + g + 8][ks * 16 + tg * 2 + 8]);
            }
#pragma unroll
            for (int nt = 0; nt < 4; nt++) {
                int cn = wn * 32 + nt * 8 + g;
                b[nt][0] = *reinterpret_cast<const unsigned*>(&Bs[cn][ks * 16 + tg * 2]);
                b[nt][1] = *reinterpret_cast<const unsigned*>(&Bs[cn][ks * 16 + tg * 2 + 8]);
            }
#pragma unroll
            for (int mt = 0; mt < 4; mt++)
#pragma unroll
                for (int nt = 0; nt < 4; nt++)
                    mma_bf16(acc[mt][nt], a[mt][0], a[mt][1], a[mt][2], a[mt][3],
                             b[nt][0], b[nt][1]);
        }
    };

    for (int k0 = 0; k0 < K; k0 += 64) {
        loadA(k0, false); loadB(Whi, k0);
        __syncthreads(); mmas(); __syncthreads();
        loadB(Wlo, k0);
        __syncthreads(); mmas(); __syncthreads();
        loadA(k0, true); loadB(Whi, k0);
        __syncthreads(); mmas(); __syncthreads();
    }

    // ---------------- epilogue ----------------
    if (LN || DOT) {
        if (t < 128) { redS[t] = 0.f; redQ[t] = 0.f; }
        __syncthreads();
    }

#pragma unroll
    for (int mt = 0; mt < 4; mt++) {
#pragma unroll
        for (int hh = 0; hh < 2; hh++) {
            int rloc = wm * 64 + mt * 16 + g + hh * 8;
            int row = rowBase + rloc;
            bool ok = row < nrows;
            int gi = (GATHER && ok) ? gidx[row] : 0;
            float partS = 0.f, partQ = 0.f;
#pragma unroll
            for (int nt = 0; nt < 4; nt++) {
                int col = wn * 32 + nt * 8 + tg * 2;
                float v0 = hh ? acc[mt][nt].z : acc[mt][nt].x;
                float v1 = hh ? acc[mt][nt].w : acc[mt][nt].y;
                if (BIAS) {
                    float2 bv = *reinterpret_cast<const float2*>(&bias[col]);
                    v0 += bv.x; v1 += bv.y;
                }
                if (GATHER) {
                    float2 gv = *reinterpret_cast<const float2*>(&gtab[(size_t)gi * 128 + col]);
                    v0 += gv.x; v1 += gv.y;
                }
                if (RES && ok) {
                    float2 rv = *reinterpret_cast<const float2*>(&Rsrc[(size_t)row * 128 + col]);
                    v0 += rv.x; v1 += rv.y;
                }
                if (SILU_ || LN) {
                    v0 = v0 / (1.f + expf(-v0));
                    v1 = v1 / (1.f + expf(-v1));
                }
                if (DOT) {
                    float2 wv = *reinterpret_cast<const float2*>(&w2[col]);
                    partS += v0 * wv.x + v1 * wv.y;
                }
                if (LN) {
                    partS += v0 + v1;
                    partQ += v0 * v0 + v1 * v1;
                    if (hh) { acc[mt][nt].z = v0; acc[mt][nt].w = v1; }
                    else    { acc[mt][nt].x = v0; acc[mt][nt].y = v1; }
                }
                if (!LN && !DOT && ok)
                    *reinterpret_cast<float2*>(&C[(size_t)row * 128 + col]) = make_float2(v0, v1);
            }
            if (LN) { atomicAdd(&redS[rloc], partS); atomicAdd(&redQ[rloc], partQ); }
            if (DOT) atomicAdd(&redS[rloc], partS);
        }
    }

    if (LN) {
        __syncthreads();
#pragma unroll
        for (int mt = 0; mt < 4; mt++) {
#pragma unroll
            for (int hh = 0; hh < 2; hh++) {
                int rloc = wm * 64 + mt * 16 + g + hh * 8;
                int row = rowBase + rloc;
                if (row >= nrows) continue;
                float mu  = redS[rloc] * (1.f / 128.f);
                float var = fmaxf(redQ[rloc] * (1.f / 128.f) - mu * mu, 0.f);
                float rs  = rsqrtf(var + LNEPS);
#pragma unroll
                for (int nt = 0; nt < 4; nt++) {
                    int col = wn * 32 + nt * 8 + tg * 2;
                    float s0 = hh ? acc[mt][nt].z : acc[mt][nt].x;
                    float s1 = hh ? acc[mt][nt].w : acc[mt][nt].y;
                    float2 gg = *reinterpret_cast<const float2*>(&lng[col]);
                    float2 bb = *reinterpret_cast<const float2*>(&lnb[col]);
                    float2 hv = *reinterpret_cast<float2*>(&C[(size_t)row * 128 + col]);
                    hv.x += (s0 - mu) * rs * gg.x + bb.x;
                    hv.y += (s1 - mu) * rs * gg.y + bb.y;
                    *reinterpret_cast<float2*>(&C[(size_t)row * 128 + col]) = hv;
                }
            }
        }
    }
    if (DOT) {
        __syncthreads();
        if (t < 128) {
            int row = rowBase + t;
            if (row < nrows) C[row] = redS[t] + w2b[0];
        }
    }
}

// ---------------- graph mean pool (batch_vec sorted; one block per graph) --------
__global__ void pool_kernel(const int* __restrict__ bv) {
    int g = blockIdx.x;
    int j = threadIdx.x;   // 128 threads, one per column
    __shared__ int se[2];
    if (j < 2) {
        int target = g + j;
        int lo = 0, hi = NN;
        while (lo < hi) { int m = (lo + hi) >> 1; if (bv[m] < target) lo = m + 1; else hi = m; }
        se[j] = lo;
    }
    __syncthreads();
    int s = se[0], e = se[1];
    float acc = 0.f;
    for (int r = s; r < e; r++) acc += g_h[(size_t)r * HD + j];
    float c = (float)(e - s);
    g_gemb[(size_t)g * HD + j] = acc / fmaxf(c, 1.f);
}

// ---------------- launch ----------------
extern "C" void kernel_launch(void* const* d_in, const int* in_sizes, int n_in,
                              void* d_out, int out_size) {
    const float* x       = (const float*)d_in[0];
    const int*   ei      = (const int*)  d_in[1];
    const int*   bv      = (const int*)  d_in[2];
    const float* in_w    = (const float*)d_in[3];
    const float* in_b    = (const float*)d_in[4];
    const float* conv_w  = (const float*)d_in[5];
    const float* conv_b  = (const float*)d_in[6];
    const float* ln_g    = (const float*)d_in[7];
    const float* ln_b    = (const float*)d_in[8];
    const float* phys_w1 = (const float*)d_in[9];
    const float* phys_b1 = (const float*)d_in[10];
    const float* phys_w2 = (const float*)d_in[11];
    const float* phys_b2 = (const float*)d_in[12];
    const float* head_w1 = (const float*)d_in[13];
    const float* head_b1 = (const float*)d_in[14];
    const float* head_w2 = (const float*)d_in[15];
    const float* head_b2 = (const float*)d_in[16];
    float* out = (float*)d_out;

    float *p_h, *p_hw, *p_agg, *p_gw, *p_gemb;
    __nv_bfloat16 *p_in_hi, *p_in_lo, *p_cv_hi, *p_cv_lo;
    __nv_bfloat16 *p_p1_hi, *p_p1_lo, *p_p2_hi, *p_p2_lo;
    __nv_bfloat16 *p_ha_hi, *p_ha_lo, *p_hb_hi, *p_hb_lo;
    cudaGetSymbolAddress((void**)&p_h,    g_h);
    cudaGetSymbolAddress((void**)&p_hw,   g_hw);
    cudaGetSymbolAddress((void**)&p_agg,  g_agg);
    cudaGetSymbolAddress((void**)&p_gw,   g_gw);
    cudaGetSymbolAddress((void**)&p_gemb, g_gemb);
    cudaGetSymbolAddress((void**)&p_in_hi, w_in_hi); cudaGetSymbolAddress((void**)&p_in_lo, w_in_lo);
    cudaGetSymbolAddress((void**)&p_cv_hi, w_cv_hi); cudaGetSymbolAddress((void**)&p_cv_lo, w_cv_lo);
    cudaGetSymbolAddress((void**)&p_p1_hi, w_p1_hi); cudaGetSymbolAddress((void**)&p_p1_lo, w_p1_lo);
    cudaGetSymbolAddress((void**)&p_p2_hi, w_p2_hi); cudaGetSymbolAddress((void**)&p_p2_lo, w_p2_lo);
    cudaGetSymbolAddress((void**)&p_ha_hi, w_ha_hi); cudaGetSymbolAddress((void**)&p_ha_lo, w_ha_lo);
    cudaGetSymbolAddress((void**)&p_hb_hi, w_hb_hi); cudaGetSymbolAddress((void**)&p_hb_lo, w_hb_lo);

    const int GEMM_GRID = (NN + 127) / 128;   // 1563

    // CSR build + norms
    zero_cnt_kernel<<<(NN + 255) / 256, 256>>>();
    hist_kernel<<<(NE + 255) / 256, 256>>>(ei);
    scan_kernel<<<1, 1024>>>();
    dis_kernel<<<(NN + 255) / 256, 256>>>();
    fill_kernel<<<(NE + 255) / 256, 256>>>(ei);

    // weight conversions (tiny)
    convert_w2_kernel<<<(128 * DIN + 255) / 256, 256>>>(in_w, DIN, DIN, p_in_hi, p_in_lo);
    for (int l = 0; l < NL; l++)
        convert_w2_kernel<<<(128 * HD + 255) / 256, 256>>>(
            conv_w + (size_t)l * HD * HD, HD, HD,
            p_cv_hi + (size_t)l * 128 * HD, p_cv_lo + (size_t)l * 128 * HD);
    convert_w2_kernel<<<(128 * HD + 255) / 256, 256>>>(phys_w1, HD, HD, p_p1_hi, p_p1_lo);
    convert_w2_kernel<<<(128 * HD + 255) / 256, 256>>>(phys_w2, HD, HD, p_p2_hi, p_p2_lo);
    convert_w2_kernel<<<(128 * HD + 255) / 256, 256>>>(head_w1,      2 * HD, HD, p_ha_hi, p_ha_lo);
    convert_w2_kernel<<<(128 * HD + 255) / 256, 256>>>(head_w1 + HD, 2 * HD, HD, p_hb_hi, p_hb_lo);

    // input projection: h = x @ in_w.T + in_b
    gemm_tc<DIN, false, true, false, false, false, false><<<GEMM_GRID, 256>>>(
        x, p_in_hi, p_in_lo, in_b, nullptr, nullptr, nullptr,
        nullptr, nullptr, nullptr, nullptr, p_h, NN);

    // GCN layers: aggregate h, then GEMM + bias + silu + LN + residual (fused)
    for (int l = 0; l < NL; l++) {
        aggregate_kernel<<<(NN + 7) / 8, 256>>>();
        gemm_tc<HD, false, true, false, false, true, false><<<GEMM_GRID, 256>>>(
            p_agg, p_cv_hi + (size_t)l * 128 * HD, p_cv_lo + (size_t)l * 128 * HD,
            conv_b + l * HD, nullptr, nullptr, nullptr,
            ln_g + l * HD, ln_b + l * HD, nullptr, nullptr, p_h, NN);
    }

    // graph mean pooling over final h
    pool_kernel<<<NG, 128>>>(bv);

    // physics MLP: hw = silu(h@W1.T+b1)
    gemm_tc<HD, true, true, false, false, false, false><<<GEMM_GRID, 256>>>(
        p_h, p_p1_hi, p_p1_lo, phys_b1, nullptr, nullptr, nullptr,
        nullptr, nullptr, nullptr, nullptr, p_hw, NN);
    // tmp = h + hw@W2.T + b2   (reuse g_agg as tmp)
    gemm_tc<HD, false, true, false, true, false, false><<<GEMM_GRID, 256>>>(
        p_hw, p_p2_hi, p_p2_lo, phys_b2, nullptr, nullptr, p_h,
        nullptr, nullptr, nullptr, nullptr, p_agg, NN);

    // per-graph precompute: gw = graph_emb @ W1b.T
    gemm_tc<HD, false, false, false, false, false, false><<<NG / 128, 256>>>(
        p_gemb, p_hb_hi, p_hb_lo, nullptr, nullptr, nullptr, nullptr,
        nullptr, nullptr, nullptr, nullptr, p_gw, NG);

    // out = silu(tmp@W1a.T + b1 + gw[bv]) . w2 + b2   (fully fused)
    gemm_tc<HD, true, true, true, false, false, true><<<GEMM_GRID, 256>>>(
        p_agg, p_ha_hi, p_ha_lo, head_b1, p_gw, bv, nullptr,
        nullptr, nullptr, head_w2, head_b2, out, NN);
}

// round 9
// speedup vs baseline: 1.5616x; 1.5616x over previous
#include <cuda_runtime.h>
#include <cuda_bf16.h>
#include <cstdint>
#include <math.h>

#define NN 200000
#define NE 600000
#define NG 8192
#define DIN 64
#define HD 128
#define NL 4
#define LNEPS 1e-5f
#define NBLK 782              // ceil(NN/256)

// ---------------- scratch (device globals, no allocations) ----------------
__device__ float g_h  [(size_t)NN * HD];
__device__ float g_hw [(size_t)NN * HD];
__device__ float g_gw [(size_t)NG * HD];
__device__ float g_dis[NN];
__device__ int   g_cnt [NN];
__device__ int   g_cur [NN];
__device__ int   g_off [NN + 1];
__device__ int   g_bsum[NBLK];
__device__ int   g_srcs[NE];

__device__ __nv_bfloat16 g_h2  [(size_t)NN * 2 * HD];   // [hi(128) | lo(128)]
__device__ __nv_bfloat16 g_hw2 [(size_t)NN * 2 * HD];
__device__ __nv_bfloat16 g_tmp2[(size_t)NN * 2 * HD];
__device__ __nv_bfloat16 g_x2  [(size_t)NN * 2 * DIN];
__device__ __nv_bfloat16 g_gemb2[(size_t)NG * 2 * HD];

// weights expanded to [hi | lo | hi] along K (3K cols)
__device__ __nv_bfloat16 w3_in  [128 * 3 * DIN];
__device__ __nv_bfloat16 w3_conv[NL * 128 * 3 * HD];
__device__ __nv_bfloat16 w3_p1  [128 * 3 * HD];
__device__ __nv_bfloat16 w3_p2  [128 * 3 * HD];
__device__ __nv_bfloat16 w3_h1a [128 * 3 * HD];
__device__ __nv_bfloat16 w3_h1b [128 * 3 * HD];

// ---------------- CSR build + norms ----------------
__global__ void zero_cnt_kernel() {
    int i = blockIdx.x * blockDim.x + threadIdx.x;
    if (i < NN) { g_cnt[i] = 0; g_cur[i] = 0; }
}
__global__ void hist_kernel(const int* __restrict__ ei) {
    int e = blockIdx.x * blockDim.x + threadIdx.x;
    if (e < NE) atomicAdd(&g_cnt[ei[NE + e]], 1);
}
// blockwise exclusive scan: g_off[i] = exclusive scan within block; g_bsum[b] = block total
__global__ void scan1_kernel() {
    int i = blockIdx.x * 256 + threadIdx.x;
    int v = (i < NN) ? g_cnt[i] : 0;
    int x = v;
    int lane = threadIdx.x & 31, wid = threadIdx.x >> 5;
#pragma unroll
    for (int o = 1; o < 32; o <<= 1) {
        int y = __shfl_up_sync(0xffffffffu, x, o);
        if (lane >= o) x += y;
    }
    __shared__ int ws[8];
    if (lane == 31) ws[wid] = x;
    __syncthreads();
    if (threadIdx.x < 8) {
        int w = ws[threadIdx.x];
#pragma unroll
        for (int o = 1; o < 8; o <<= 1) {
            int y = __shfl_up_sync(0xffu, w, o);
            if ((threadIdx.x & 7) >= o) w += y;
        }
        ws[threadIdx.x] = w;
    }
    __syncthreads();
    int excl = x - v + (wid ? ws[wid - 1] : 0);
    if (i < NN) g_off[i] = excl;
    if (threadIdx.x == 255) g_bsum[blockIdx.x] = excl + v;
}
// exclusive scan of block sums (one block, 1024 threads; NBLK <= 1024)
__global__ void scan2_kernel() {
    __shared__ int sh[1024];
    int t = threadIdx.x;
    sh[t] = (t < NBLK) ? g_bsum[t] : 0;
    __syncthreads();
    int lane = t & 31, wid = t >> 5;
    int v = sh[t], x = v;
#pragma unroll
    for (int o = 1; o < 32; o <<= 1) {
        int y = __shfl_up_sync(0xffffffffu, x, o);
        if (lane >= o) x += y;
    }
    __shared__ int ws[32];
    if (lane == 31) ws[wid] = x;
    __syncthreads();
    if (t < 32) {
        int w = ws[t];
#pragma unroll
        for (int o = 1; o < 32; o <<= 1) {
            int y = __shfl_up_sync(0xffffffffu, w, o);
            if (lane >= o) w += y;
        }
        ws[t] = w;
    }
    __syncthreads();
    int excl = x - v + (wid ? ws[wid - 1] : 0);
    if (t < NBLK) g_bsum[t] = excl;
    if (t == 0) g_off[NN] = NE;
}
__global__ void scan3_kernel() {
    int i = blockIdx.x * 256 + threadIdx.x;
    if (i < NN) g_off[i] += g_bsum[blockIdx.x];
}
__global__ void dis_kernel() {
    int i = blockIdx.x * blockDim.x + threadIdx.x;
    if (i < NN) g_dis[i] = rsqrtf((float)g_cnt[i] + 1.f);
}
__global__ void fill_kernel(const int* __restrict__ ei) {
    int e = blockIdx.x * blockDim.x + threadIdx.x;
    if (e >= NE) return;
    int s = ei[e], d = ei[NE + e];
    int pos = g_off[d] + atomicAdd(&g_cur[d], 1);
    g_srcs[pos] = s;
}

// ---------------- conversions ----------------
__device__ __forceinline__ void split_bf16(float v, __nv_bfloat16& hi, __nv_bfloat16& lo) {
    hi = __float2bfloat16(v);
    lo = __float2bfloat16(v - __bfloat162float(hi));
}

__global__ void convert_x_kernel(const float* __restrict__ x) {
    int i = blockIdx.x * blockDim.x + threadIdx.x;
    if (i >= NN * DIN) return;
    int n = i >> 6, k = i & 63;
    __nv_bfloat16 hi, lo;
    split_bf16(x[i], hi, lo);
    g_x2[(size_t)n * 128 + k]      = hi;
    g_x2[(size_t)n * 128 + 64 + k] = lo;
}

__global__ void convert_w_kernel(const float* __restrict__ src, int lds, int K, int rows,
                                 __nv_bfloat16* __restrict__ dst) {
    int i = blockIdx.x * blockDim.x + threadIdx.x;
    if (i >= rows * K) return;
    int j = i / K, k = i - j * K;
    __nv_bfloat16 hi, lo;
    split_bf16(src[(size_t)j * lds + k], hi, lo);
    size_t b = (size_t)j * 3 * K;
    dst[b + k]         = hi;
    dst[b + K + k]     = lo;
    dst[b + 2 * K + k] = hi;
}

// ---------------- tensor-core GEMM (bf16x3, fp32 accum) ----------------
__device__ __forceinline__ void mma_bf16(float4& c, unsigned a0, unsigned a1, unsigned a2,
                                         unsigned a3, unsigned b0, unsigned b1) {
    asm volatile(
        "mma.sync.aligned.m16n8k16.row.col.f32.bf16.bf16.f32 "
        "{%0,%1,%2,%3}, {%4,%5,%6,%7}, {%8,%9}, {%0,%1,%2,%3};"
        : "+f"(c.x), "+f"(c.y), "+f"(c.z), "+f"(c.w)
        : "r"(a0), "r"(a1), "r"(a2), "r"(a3), "r"(b0), "r"(b1));
}

template<int K, bool SILU_, bool BIAS, bool GATHER, bool RES, bool WF32, bool WBF>
__launch_bounds__(256)
__global__ void gemm_bf16(const __nv_bfloat16* __restrict__ A2,
                          const __nv_bfloat16* __restrict__ B3,
                          const float* __restrict__ bias,
                          const float* __restrict__ gtab, const int* __restrict__ gidx,
                          const float* __restrict__ Rsrc,
                          float* __restrict__ C, __nv_bfloat16* __restrict__ C2,
                          int nrows)
{
    constexpr int LDA = 2 * K;
    constexpr int LDB = 3 * K;
    constexpr int NC  = (3 * K) / 64;     // 64-wide k chunks

    __shared__ __nv_bfloat16 As[128][72];
    __shared__ __nv_bfloat16 Bs[128][72];

    const int t    = threadIdx.x;
    const int lane = t & 31;
    const int wid  = t >> 5;
    const int wm   = wid >> 2;    // 0..1  (64 rows each)
    const int wn   = wid & 3;     // 0..3  (32 cols each)
    const int g    = lane >> 2;   // 0..7
    const int tg   = lane & 3;    // 0..3
    const int rowBase = blockIdx.x * 128;

    float4 acc[4][4];
#pragma unroll
    for (int i = 0; i < 4; i++)
#pragma unroll
        for (int j = 0; j < 4; j++) acc[i][j] = make_float4(0.f, 0.f, 0.f, 0.f);

    for (int c = 0; c < NC; c++) {
        const int k0  = c * 64;
        const int seg = k0 / K;
        const int aOff = (seg == 2 ? K : 0) + (k0 - seg * K);   // A: hi,hi,lo
#pragma unroll
        for (int q = 0; q < 4; q++) {
            int f = t + 256 * q;
            int r = f >> 3, sub = f & 7;
            uint4 v = make_uint4(0u, 0u, 0u, 0u);
            int grow = rowBase + r;
            if (grow < nrows)
                v = *reinterpret_cast<const uint4*>(&A2[(size_t)grow * LDA + aOff + sub * 8]);
            *reinterpret_cast<uint4*>(&As[r][sub * 8]) = v;
            uint4 w = *reinterpret_cast<const uint4*>(&B3[(size_t)r * LDB + k0 + sub * 8]);
            *reinterpret_cast<uint4*>(&Bs[r][sub * 8]) = w;
        }
        __syncthreads();
#pragma unroll
        for (int ks = 0; ks < 4; ks++) {
            unsigned a[4][4], b[4][2];
#pragma unroll
            for (int mt = 0; mt < 4; mt++) {
                int rm = wm * 64 + mt * 16;
                a[mt][0] = *reinterpret_cast<const unsigned*>(&As[rm + g    ][ks * 16 + tg * 2]);
                a[mt][1] = *reinterpret_cast<const unsigned*>(&As[rm + g + 8][ks * 16 + tg * 2]);
                a[mt][2] = *reinterpret_cast<const unsigned*>(&As[rm + g    ][ks * 16 + tg * 2 + 8]);
                a[mt][3] = *reinterpret_cast<const unsigned*>(&As[rm + g + 8][ks * 16 + tg * 2 + 8]);
            }
#pragma unroll
            for (int nt = 0; nt < 4; nt++) {
                int cn = wn * 32 + nt * 8 + g;
                b[nt][0] = *reinterpret_cast<const unsigned*>(&Bs[cn][ks * 16 + tg * 2]);
                b[nt][1] = *reinterpret_cast<const unsigned*>(&Bs[cn][ks * 16 + tg * 2 + 8]);
            }
#pragma unroll
            for (int mt = 0; mt < 4; mt++)
#pragma unroll
                for (int nt = 0; nt < 4; nt++)
                    mma_bf16(acc[mt][nt], a[mt][0], a[mt][1], a[mt][2], a[mt][3],
                             b[nt][0], b[nt][1]);
        }
        __syncthreads();
    }

    // epilogue
#pragma unroll
    for (int mt = 0; mt < 4; mt++) {
#pragma unroll
        for (int hh = 0; hh < 2; hh++) {
            int row = rowBase + wm * 64 + mt * 16 + g + hh * 8;
            if (row >= nrows) continue;
            int gi = 0;
            if (GATHER) gi = gidx[row];
#pragma unroll
            for (int nt = 0; nt < 4; nt++) {
                int col = wn * 32 + nt * 8 + tg * 2;
                float v0 = hh ? acc[mt][nt].z : acc[mt][nt].x;
                float v1 = hh ? acc[mt][nt].w : acc[mt][nt].y;
                if (BIAS) {
                    float2 bv = *reinterpret_cast<const float2*>(&bias[col]);
                    v0 += bv.x; v1 += bv.y;
                }
                if (GATHER) {
                    float2 gv = *reinterpret_cast<const float2*>(&gtab[(size_t)gi * 128 + col]);
                    v0 += gv.x; v1 += gv.y;
                }
                if (RES) {
                    float2 rv = *reinterpret_cast<const float2*>(&Rsrc[(size_t)row * 128 + col]);
                    v0 += rv.x; v1 += rv.y;
                }
                if (SILU_) {
                    v0 = v0 / (1.f + expf(-v0));
                    v1 = v1 / (1.f + expf(-v1));
                }
                if (WF32)
                    *reinterpret_cast<float2*>(&C[(size_t)row * 128 + col]) = make_float2(v0, v1);
                if (WBF) {
                    __nv_bfloat16 h0, l0, h1, l1;
                    split_bf16(v0, h0, l0);
                    split_bf16(v1, h1, l1);
                    *reinterpret_cast<__nv_bfloat162*>(&C2[(size_t)row * 256 + col]) =
                        __halves2bfloat162(h0, h1);
                    *reinterpret_cast<__nv_bfloat162*>(&C2[(size_t)row * 256 + 128 + col]) =
                        __halves2bfloat162(l0, l1);
                }
            }
        }
    }
}

// ---------------- fused: agg (CSR gather) + silu + LN + residual ----------------
// agg[d] = hw[d]*dis[d]^2 + conv_b + sum_{s in CSR[d]} hw[s]*dis[s]*dis[d]
// h[d]  += LN(silu(agg)) * g + b ;  also writes bf16 hi/lo mirror of h.
__global__ void agg_silu_ln_kernel(const float* __restrict__ cb,
                                   const float* __restrict__ lng,
                                   const float* __restrict__ lnb) {
    int d = (blockIdx.x * blockDim.x + threadIdx.x) >> 5;
    int lane = threadIdx.x & 31;
    if (d >= NN) return;
    size_t base = (size_t)d * HD + lane * 4;
    float dd = g_dis[d];
    float sn = dd * dd;
    float4 acc = *reinterpret_cast<const float4*>(&g_hw[base]);
    float4 cb4 = *reinterpret_cast<const float4*>(&cb[lane * 4]);
    acc.x = acc.x * sn + cb4.x; acc.y = acc.y * sn + cb4.y;
    acc.z = acc.z * sn + cb4.z; acc.w = acc.w * sn + cb4.w;
    int beg = g_off[d], end = g_off[d + 1];
    for (int e = beg; e < end; e++) {
        int s = g_srcs[e];
        float ne = g_dis[s] * dd;
        float4 v = *reinterpret_cast<const float4*>(&g_hw[(size_t)s * HD + lane * 4]);
        acc.x += v.x * ne; acc.y += v.y * ne; acc.z += v.z * ne; acc.w += v.w * ne;
    }
    // silu
    float4 s4;
    s4.x = acc.x / (1.f + expf(-acc.x));
    s4.y = acc.y / (1.f + expf(-acc.y));
    s4.z = acc.z / (1.f + expf(-acc.z));
    s4.w = acc.w / (1.f + expf(-acc.w));
    float sum = s4.x + s4.y + s4.z + s4.w;
#pragma unroll
    for (int o = 16; o; o >>= 1) sum += __shfl_xor_sync(0xFFFFFFFFu, sum, o);
    float mu = sum * (1.f / HD);
    float dx = s4.x - mu, dy = s4.y - mu, dz = s4.z - mu, dw = s4.w - mu;
    float sq = dx * dx + dy * dy + dz * dz + dw * dw;
#pragma unroll
    for (int o = 16; o; o >>= 1) sq += __shfl_xor_sync(0xFFFFFFFFu, sq, o);
    float r = rsqrtf(sq * (1.f / HD) + LNEPS);
    float4 g4 = *reinterpret_cast<const float4*>(&lng[lane * 4]);
    float4 b4 = *reinterpret_cast<const float4*>(&lnb[lane * 4]);
    float4 h = *reinterpret_cast<const float4*>(&g_h[base]);
    h.x += dx * r * g4.x + b4.x;
    h.y += dy * r * g4.y + b4.y;
    h.z += dz * r * g4.z + b4.z;
    h.w += dw * r * g4.w + b4.w;
    *reinterpret_cast<float4*>(&g_h[base]) = h;
    __nv_bfloat16 hi0, lo0, hi1, lo1, hi2, lo2, hi3, lo3;
    split_bf16(h.x, hi0, lo0); split_bf16(h.y, hi1, lo1);
    split_bf16(h.z, hi2, lo2); split_bf16(h.w, hi3, lo3);
    size_t b2 = (size_t)d * 256 + lane * 4;
    *reinterpret_cast<__nv_bfloat162*>(&g_h2[b2])           = __halves2bfloat162(hi0, hi1);
    *reinterpret_cast<__nv_bfloat162*>(&g_h2[b2 + 2])       = __halves2bfloat162(hi2, hi3);
    *reinterpret_cast<__nv_bfloat162*>(&g_h2[b2 + 128])     = __halves2bfloat162(lo0, lo1);
    *reinterpret_cast<__nv_bfloat162*>(&g_h2[b2 + 128 + 2]) = __halves2bfloat162(lo2, lo3);
}

// ---------------- graph mean pool (batch_vec sorted; one block per graph) --------
__global__ void pool_kernel(const int* __restrict__ bv) {
    int g = blockIdx.x;
    int j = threadIdx.x;   // 128 threads, one per column
    __shared__ int se[2];
    if (j < 2) {
        int target = g + j;
        int lo = 0, hi = NN;
        while (lo < hi) { int m = (lo + hi) >> 1; if (bv[m] < target) lo = m + 1; else hi = m; }
        se[j] = lo;
    }
    __syncthreads();
    int s = se[0], e = se[1];
    float acc = 0.f;
    for (int r = s; r < e; r++) acc += g_h[(size_t)r * HD + j];
    float c = (float)(e - s);
    float v = acc / fmaxf(c, 1.f);
    __nv_bfloat16 hi, lo;
    split_bf16(v, hi, lo);
    g_gemb2[(size_t)g * 256 + j]       = hi;
    g_gemb2[(size_t)g * 256 + 128 + j] = lo;
}

// ---------------- final projection to scalar (warp per row) ----------------
__global__ void head_out_kernel(const float* __restrict__ w2, const float* __restrict__ b2,
                                float* __restrict__ out) {
    int row = (blockIdx.x * blockDim.x + threadIdx.x) >> 5;
    int lane = threadIdx.x & 31;
    if (row >= NN) return;
    float4 v = *reinterpret_cast<const float4*>(&g_hw[(size_t)row * HD + lane * 4]);
    float4 u = *reinterpret_cast<const float4*>(&w2[lane * 4]);
    float s = v.x * u.x + v.y * u.y + v.z * u.z + v.w * u.w;
#pragma unroll
    for (int o = 16; o; o >>= 1) s += __shfl_xor_sync(0xFFFFFFFFu, s, o);
    if (lane == 0) out[row] = s + b2[0];
}

// ---------------- launch ----------------
extern "C" void kernel_launch(void* const* d_in, const int* in_sizes, int n_in,
                              void* d_out, int out_size) {
    const float* x       = (const float*)d_in[0];
    const int*   ei      = (const int*)  d_in[1];
    const int*   bv      = (const int*)  d_in[2];
    const float* in_w    = (const float*)d_in[3];
    const float* in_b    = (const float*)d_in[4];
    const float* conv_w  = (const float*)d_in[5];
    const float* conv_b  = (const float*)d_in[6];
    const float* ln_g    = (const float*)d_in[7];
    const float* ln_b    = (const float*)d_in[8];
    const float* phys_w1 = (const float*)d_in[9];
    const float* phys_b1 = (const float*)d_in[10];
    const float* phys_w2 = (const float*)d_in[11];
    const float* phys_b2 = (const float*)d_in[12];
    const float* head_w1 = (const float*)d_in[13];
    const float* head_b1 = (const float*)d_in[14];
    const float* head_w2 = (const float*)d_in[15];
    const float* head_b2 = (const float*)d_in[16];
    float* out = (float*)d_out;

    float *p_h, *p_hw, *p_gw;
    __nv_bfloat16 *p_h2, *p_hw2, *p_tmp2, *p_x2, *p_gemb2;
    __nv_bfloat16 *p_w3in, *p_w3conv, *p_w3p1, *p_w3p2, *p_w3h1a, *p_w3h1b;
    cudaGetSymbolAddress((void**)&p_h,     g_h);
    cudaGetSymbolAddress((void**)&p_hw,    g_hw);
    cudaGetSymbolAddress((void**)&p_gw,    g_gw);
    cudaGetSymbolAddress((void**)&p_h2,    g_h2);
    cudaGetSymbolAddress((void**)&p_hw2,   g_hw2);
    cudaGetSymbolAddress((void**)&p_tmp2,  g_tmp2);
    cudaGetSymbolAddress((void**)&p_x2,    g_x2);
    cudaGetSymbolAddress((void**)&p_gemb2, g_gemb2);
    cudaGetSymbolAddress((void**)&p_w3in,  w3_in);
    cudaGetSymbolAddress((void**)&p_w3conv,w3_conv);
    cudaGetSymbolAddress((void**)&p_w3p1,  w3_p1);
    cudaGetSymbolAddress((void**)&p_w3p2,  w3_p2);
    cudaGetSymbolAddress((void**)&p_w3h1a, w3_h1a);
    cudaGetSymbolAddress((void**)&p_w3h1b, w3_h1b);

    const int GEMM_GRID = (NN + 127) / 128;          // 1563
    const int WCONV_GRID = (128 * HD + 255) / 256;

    // CSR build + norms
    zero_cnt_kernel<<<(NN + 255) / 256, 256>>>();
    hist_kernel<<<(NE + 255) / 256, 256>>>(ei);
    scan1_kernel<<<NBLK, 256>>>();
    scan2_kernel<<<1, 1024>>>();
    scan3_kernel<<<NBLK, 256>>>();
    dis_kernel<<<(NN + 255) / 256, 256>>>();
    fill_kernel<<<(NE + 255) / 256, 256>>>(ei);

    // conversions
    convert_x_kernel<<<(NN * DIN + 255) / 256, 256>>>(x);
    convert_w_kernel<<<(128 * DIN + 255) / 256, 256>>>(in_w, DIN, DIN, 128, p_w3in);
    for (int l = 0; l < NL; l++)
        convert_w_kernel<<<WCONV_GRID, 256>>>(conv_w + (size_t)l * HD * HD, HD, HD, 128,
                                              p_w3conv + (size_t)l * 128 * 3 * HD);
    convert_w_kernel<<<WCONV_GRID, 256>>>(phys_w1, HD, HD, 128, p_w3p1);
    convert_w_kernel<<<WCONV_GRID, 256>>>(phys_w2, HD, HD, 128, p_w3p2);
    convert_w_kernel<<<WCONV_GRID, 256>>>(head_w1,      2 * HD, HD, 128, p_w3h1a);
    convert_w_kernel<<<WCONV_GRID, 256>>>(head_w1 + HD, 2 * HD, HD, 128, p_w3h1b);

    // input projection: h = x @ in_w.T + in_b  (write f32 + bf16)
    gemm_bf16<DIN, false, true, false, false, true, true><<<GEMM_GRID, 256>>>(
        p_x2, p_w3in, in_b, nullptr, nullptr, nullptr, p_h, p_h2, NN);

    // GCN layers: GEMM (hw = h@W.T, f32 only) then fused CSR-agg + silu + LN + residual
    for (int l = 0; l < NL; l++) {
        gemm_bf16<HD, false, false, false, false, true, false><<<GEMM_GRID, 256>>>(
            p_h2, p_w3conv + (size_t)l * 128 * 3 * HD, nullptr,
            nullptr, nullptr, nullptr, p_hw, nullptr, NN);
        agg_silu_ln_kernel<<<(NN + 7) / 8, 256>>>(conv_b + l * HD, ln_g + l * HD, ln_b + l * HD);
    }

    // graph mean pooling over final h
    pool_kernel<<<NG, 128>>>(bv);

    // physics MLP: hw2 = silu(h@W1.T+b1) (bf16 only)
    gemm_bf16<HD, true, true, false, false, false, true><<<GEMM_GRID, 256>>>(
        p_h2, p_w3p1, phys_b1, nullptr, nullptr, nullptr, nullptr, p_hw2, NN);
    // tmp2 = h + hw@W2.T + b2 (bf16 only)
    gemm_bf16<HD, false, true, false, true, false, true><<<GEMM_GRID, 256>>>(
        p_hw2, p_w3p2, phys_b2, nullptr, nullptr, p_h, nullptr, p_tmp2, NN);

    // per-graph precompute: gw = graph_emb @ W1b.T
    gemm_bf16<HD, false, false, false, false, true, false><<<NG / 128, 256>>>(
        p_gemb2, p_w3h1b, nullptr, nullptr, nullptr, nullptr, p_gw, nullptr, NG);

    // hid = silu( tmp @ W1a.T + gw[batch] + b1 )  -> g_hw (f32)
    gemm_bf16<HD, true, true, true, false, true, false><<<GEMM_GRID, 256>>>(
        p_tmp2, p_w3h1a, head_b1, p_gw, bv, nullptr, p_hw, nullptr, NN);

    // out = hid @ w2.T + b2
    head_out_kernel<<<(NN + 7) / 8, 256>>>(head_w2, head_b2, out);
}